// round 9
// baseline (speedup 1.0000x reference)
#include <cuda_runtime.h>
#include <stdint.h>

// SeqOperation: out[b,i,:] = seq[b,p,:]     if i == (p+1) % n         (ungated)
//                          = seq[b,i,:]     if p<=n-3 && i < p
//                          = seq[b,i-2,:]   if p<=n-3 && i >= p+3
//                          = 0              otherwise
// p = pos_idx[b] (int32 on device). seq: (B=4096, n=200, d=128) f32.
// Bandwidth-bound, ~830 MB min traffic.
// R3: MLP=1 -> 145.8us @69.8% DRAM. R5: MLP=2 -> 123.4 @83.2%. R6: MLP=4 flat.
// This round: streaming cache hints (ldcs/stcs) — data touched exactly once.

constexpr int N_SEQ = 200;
constexpr int D4    = 32;            // d=128 floats = 32 float4 per row
constexpr int ROWS_PER_WARP   = 4;
constexpr int WARPS_PER_BLOCK = 8;   // 256 threads
constexpr int ROWS_PER_BLOCK  = ROWS_PER_WARP * WARPS_PER_BLOCK;  // 32

__device__ __forceinline__ int src_row(int i, int p)
{
    // returns source row index within batch, or -1 for zero-fill
    bool valid = (p <= N_SEQ - 3);
    int pp1 = (p + 1 == N_SEQ) ? 0 : (p + 1);
    if (i == pp1) return p;                    // rolled "pos" term, NOT gated
    if (valid) {
        if (i < p)      return i;              // left term
        if (i >= p + 3) return i - 2;          // rolled "right" term
    }
    return -1;
}

__global__ __launch_bounds__(256)
void seqop_kernel(const float4* __restrict__ seq,
                  const int* __restrict__ pos_idx,
                  float4* __restrict__ out,
                  int total_rows)
{
    int warp = blockIdx.x * WARPS_PER_BLOCK + (threadIdx.x >> 5);
    int lane = threadIdx.x & 31;
    int r0   = warp * ROWS_PER_WARP;
    if (r0 >= total_rows) return;

    int src[ROWS_PER_WARP];

    #pragma unroll
    for (int k = 0; k < ROWS_PER_WARP; k++) {
        int r = r0 + k;
        int b = r / N_SEQ;
        int i = r - b * N_SEQ;
        int p = __ldg(&pos_idx[b]);            // tiny, reused -> keep cached
        src[k] = src_row(i, p);
        if (src[k] >= 0) src[k] += b * N_SEQ;  // absolute source row
    }

    // Front-batch all loads (MLP=4), evict-first: each seq row is read once.
    float4 v[ROWS_PER_WARP];
    #pragma unroll
    for (int k = 0; k < ROWS_PER_WARP; k++) {
        v[k] = make_float4(0.f, 0.f, 0.f, 0.f);
        if (src[k] >= 0)
            v[k] = __ldcs(&seq[src[k] * D4 + lane]);
    }

    // Streaming stores: output is never re-read by this kernel.
    #pragma unroll
    for (int k = 0; k < ROWS_PER_WARP; k++) {
        __stcs(&out[(r0 + k) * D4 + lane], v[k]);   // always write: poisoned
    }
}

extern "C" void kernel_launch(void* const* d_in, const int* in_sizes, int n_in,
                              void* d_out, int out_size)
{
    const float4* seq = (const float4*)d_in[0];
    const int*    pos = (const int*)d_in[1];
    float4*       o   = (float4*)d_out;

    int B = in_sizes[1];                 // 4096
    int total_rows = B * N_SEQ;          // 819200

    int grid = (total_rows + ROWS_PER_BLOCK - 1) / ROWS_PER_BLOCK;  // 25600
    seqop_kernel<<<grid, 256>>>(seq, pos, o, total_rows);
}

// round 10
// speedup vs baseline: 1.0010x; 1.0010x over previous
#include <cuda_runtime.h>
#include <stdint.h>

// SeqOperation: out[b,i,:] = seq[b,p,:]     if i == (p+1) % n         (ungated)
//                          = seq[b,i,:]     if p<=n-3 && i < p
//                          = seq[b,i-2,:]   if p<=n-3 && i >= p+3
//                          = 0              otherwise
// p = pos_idx[b] (int32 on device). seq: (B=4096, n=200, d=128) f32.
// Bandwidth-bound, ~830 MB min traffic. History:
//   R3 MLP=1: 145.8us @69.8% DRAM | R5 MLP=2: 123.4 @83.2% | R6 MLP=4: flat
//   R9 ldcs/stcs: flat -> pinned at HBM R/W ceiling (~6.6 TB/s).
// This round: 512-thread blocks (half the CTAs) to trim wave/launch overhead;
// default cache policy restored.

constexpr int N_SEQ = 200;
constexpr int D4    = 32;            // d=128 floats = 32 float4 per row
constexpr int ROWS_PER_WARP   = 4;
constexpr int WARPS_PER_BLOCK = 16;  // 512 threads
constexpr int ROWS_PER_BLOCK  = ROWS_PER_WARP * WARPS_PER_BLOCK;  // 64

__device__ __forceinline__ int src_row(int i, int p)
{
    // returns source row index within batch, or -1 for zero-fill
    bool valid = (p <= N_SEQ - 3);
    int pp1 = (p + 1 == N_SEQ) ? 0 : (p + 1);
    if (i == pp1) return p;                    // rolled "pos" term, NOT gated
    if (valid) {
        if (i < p)      return i;              // left term
        if (i >= p + 3) return i - 2;          // rolled "right" term
    }
    return -1;
}

__global__ __launch_bounds__(512)
void seqop_kernel(const float4* __restrict__ seq,
                  const int* __restrict__ pos_idx,
                  float4* __restrict__ out,
                  int total_rows)
{
    int warp = blockIdx.x * WARPS_PER_BLOCK + (threadIdx.x >> 5);
    int lane = threadIdx.x & 31;
    int r0   = warp * ROWS_PER_WARP;
    if (r0 >= total_rows) return;

    int src[ROWS_PER_WARP];

    #pragma unroll
    for (int k = 0; k < ROWS_PER_WARP; k++) {
        int r = r0 + k;
        int b = r / N_SEQ;
        int i = r - b * N_SEQ;
        int p = __ldg(&pos_idx[b]);
        src[k] = src_row(i, p);
        if (src[k] >= 0) src[k] += b * N_SEQ;  // absolute source row
    }

    // Front-batch all loads so they are concurrently in flight (MLP=4).
    float4 v[ROWS_PER_WARP];
    #pragma unroll
    for (int k = 0; k < ROWS_PER_WARP; k++) {
        v[k] = make_float4(0.f, 0.f, 0.f, 0.f);
        if (src[k] >= 0)
            v[k] = __ldg(&seq[src[k] * D4 + lane]);
    }

    #pragma unroll
    for (int k = 0; k < ROWS_PER_WARP; k++) {
        out[(r0 + k) * D4 + lane] = v[k];      // always write: d_out poisoned
    }
}

extern "C" void kernel_launch(void* const* d_in, const int* in_sizes, int n_in,
                              void* d_out, int out_size)
{
    const float4* seq = (const float4*)d_in[0];
    const int*    pos = (const int*)d_in[1];
    float4*       o   = (float4*)d_out;

    int B = in_sizes[1];                 // 4096
    int total_rows = B * N_SEQ;          // 819200

    int grid = (total_rows + ROWS_PER_BLOCK - 1) / ROWS_PER_BLOCK;  // 12800
    seqop_kernel<<<grid, 512>>>(seq, pos, o, total_rows);
}

// round 11
// speedup vs baseline: 1.0036x; 1.0026x over previous
#include <cuda_runtime.h>
#include <stdint.h>

// SeqOperation_28106265985064 — FINAL (converged at HBM R/W ceiling).
//
// Algebraic collapse of the reference (one-hot/roll/where chain) into a
// per-row gather, p = pos_idx[b] (int32 on device):
//   out[b,i,:] = seq[b,p,:]     if i == (p+1) % n          (ungated)
//              = seq[b,i,:]     if p<=n-3 && i < p
//              = seq[b,i-2,:]   if p<=n-3 && i >= p+3
//              = 0              otherwise
// seq: (B=4096, n=200, d=128) f32. ~830 MB minimal traffic (read once + write).
//
// Session history:
//   R3  warp/row, MLP=1           : 145.8us @ 69.8% DRAM (latency-exposed)
//   R5  2 rows/warp, MLP=2        : 123.4us @ 83.2% DRAM  <- WIN, kept
//   R6  MLP=4                     : flat  (latency lever exhausted)
//   R9  __ldcs/__stcs streaming   : flat  (cache policy non-binding)
//   R10 512-thread blocks         : flat  (occupancy/waves non-binding)
// Conclusion: pinned at ~6.6 TB/s achieved HBM mixed-R/W throughput; traffic
// already minimal; LTS cap is path-independent (TMA gains nothing).

constexpr int N_SEQ = 200;
constexpr int D4    = 32;            // d=128 floats = 32 float4 per row
constexpr int ROWS_PER_WARP   = 2;
constexpr int WARPS_PER_BLOCK = 8;   // 256 threads
constexpr int ROWS_PER_BLOCK  = ROWS_PER_WARP * WARPS_PER_BLOCK;  // 16

__device__ __forceinline__ int src_row(int i, int p)
{
    // source row within batch, or -1 for zero-fill
    bool valid = (p <= N_SEQ - 3);
    int pp1 = (p + 1 == N_SEQ) ? 0 : (p + 1);
    if (i == pp1) return p;                    // rolled "pos" term, NOT gated
    if (valid) {
        if (i < p)      return i;              // left term
        if (i >= p + 3) return i - 2;          // rolled "right" term
    }
    return -1;
}

__global__ __launch_bounds__(256)
void seqop_kernel(const float4* __restrict__ seq,
                  const int* __restrict__ pos_idx,
                  float4* __restrict__ out,
                  int total_rows)
{
    int warp = blockIdx.x * WARPS_PER_BLOCK + (threadIdx.x >> 5);
    int lane = threadIdx.x & 31;
    int r0   = warp * ROWS_PER_WARP;
    if (r0 >= total_rows) return;

    int src[ROWS_PER_WARP];

    #pragma unroll
    for (int k = 0; k < ROWS_PER_WARP; k++) {
        int r = r0 + k;
        int b = r / N_SEQ;
        int i = r - b * N_SEQ;
        int p = __ldg(&pos_idx[b]);
        src[k] = src_row(i, p);
        if (src[k] >= 0) src[k] += b * N_SEQ;  // absolute source row
    }

    // Front-batch loads so both LDG.128 are concurrently in flight (MLP=2):
    // this is the change that took DRAM from 69.8% to 83.2% of peak.
    float4 v[ROWS_PER_WARP];
    #pragma unroll
    for (int k = 0; k < ROWS_PER_WARP; k++) {
        v[k] = make_float4(0.f, 0.f, 0.f, 0.f);
        if (src[k] >= 0)
            v[k] = __ldg(&seq[src[k] * D4 + lane]);
    }

    #pragma unroll
    for (int k = 0; k < ROWS_PER_WARP; k++) {
        out[(r0 + k) * D4 + lane] = v[k];      // always write: d_out poisoned
    }
}

extern "C" void kernel_launch(void* const* d_in, const int* in_sizes, int n_in,
                              void* d_out, int out_size)
{
    const float4* seq = (const float4*)d_in[0];
    const int*    pos = (const int*)d_in[1];
    float4*       o   = (float4*)d_out;

    int B = in_sizes[1];                 // 4096
    int total_rows = B * N_SEQ;          // 819200

    int grid = (total_rows + ROWS_PER_BLOCK - 1) / ROWS_PER_BLOCK;  // 51200
    seqop_kernel<<<grid, 256>>>(seq, pos, o, total_rows);
}